// round 10
// baseline (speedup 1.0000x reference)
#include <cuda_runtime.h>
#include <cstdint>
#include <cstddef>

// router_20091857011524: fused 4-way router (GB300 sm_103a) — R10
// R9 + prefetch.global.L2 with a 6-group lead. The depth-1 register
// prefetch then hits L2 (~250cyc) instead of DRAM (~577+), and the
// DRAM->L2 pipeline per warp carries ~12KB in flight at zero register /
// smem / scoreboard cost. Everything else identical to R9:
// warp owns 4 tokens (lane = t*8+j), W staged once into 64KB smem with
// dim permutation -> conflict-free 128B-broadcast LDS, shfl_xor logit
// reduce, per-lane epilogue, L2-hot phase C.

#define THREADS 256
#define TPB_TOK 32          // 8 warps x 4 tokens
#define NG 16               // 512 dims / 32 per group
#define PF_LEAD 6           // prefetch lead distance (groups)

#define SMEM_FLOATS (8 * 512 * 4)     // 8 o-planes x 512 float4
#define SMEM_BYTES  (SMEM_FLOATS * 4) // 65536

__device__ __forceinline__ void pfL2(const void* p) {
    asm volatile("prefetch.global.L2 [%0];" :: "l"(p));
}

__global__ __launch_bounds__(THREADS)
void router_kernel(const float* __restrict__ m0, const float* __restrict__ m1,
                   const float* __restrict__ m2, const float* __restrict__ m3,
                   const float* __restrict__ Wt, const float* __restrict__ bt,
                   const float* __restrict__ Ws, const float* __restrict__ bs,
                   const float* __restrict__ alpha, float* __restrict__ out)
{
    extern __shared__ float smem[];
    float4* wsm = reinterpret_cast<float4*>(smem);

    const int tid  = threadIdx.x;
    const int lane = tid & 31;
    const int wrp  = tid >> 5;
    const int t    = lane >> 3;    // token within warp (0..3)
    const int j    = lane & 7;     // dim slot (0..7)

    // ---- stage W once: wsm[o*512 + g*32 + jj*8 + js], where for dim d:
    // g = d>>5, js = (d>>2)&7, jj = d&3.  Lane j owns dims g*32 + j*4 + jj.
    {
        const float4* wt4 = reinterpret_cast<const float4*>(Wt);
        const float4* ws4 = reinterpret_cast<const float4*>(Ws);
        #pragma unroll
        for (int rep = 0; rep < 16; rep++) {
            const int i  = tid + rep * THREADS;   // 0..4095
            const int o  = i >> 9;
            const int dd = i & 511;
            float4 v = (o < 4) ? __ldg(wt4 + o * 512 + dd)
                               : __ldg(ws4 + (o - 4) * 512 + dd);
            const int g = dd >> 5, jj = dd & 3, js = (dd >> 2) & 7;
            wsm[o * 512 + g * 32 + jj * 8 + js] = v;
        }
    }
    __syncthreads();   // the ONLY block barrier

    const int tok = blockIdx.x * TPB_TOK + wrp * 4 + t;
    const size_t row = (size_t)tok * 512;
    const float4* q0 = reinterpret_cast<const float4*>(m0 + row);
    const float4* q1 = reinterpret_cast<const float4*>(m1 + row);
    const float4* q2 = reinterpret_cast<const float4*>(m2 + row);
    const float4* q3 = reinterpret_cast<const float4*>(m3 + row);

    float acc[8];
    #pragma unroll
    for (int o = 0; o < 8; o++) acc[o] = 0.f;

    // ---- prologue: L2-prefetch groups 1..PF_LEAD (no state, no scoreboard)
    #pragma unroll
    for (int g = 1; g <= PF_LEAD; g++) {
        const int idx = g * 8 + j;
        pfL2(q0 + idx); pfL2(q1 + idx); pfL2(q2 + idx); pfL2(q3 + idx);
    }

    // ---- main loop: LDG.128 direct to regs, depth-1 register prefetch,
    //      L2 prefetch running PF_LEAD groups ahead.
    float4 c0 = __ldg(q0 + j);
    float4 c1 = __ldg(q1 + j);
    float4 c2 = __ldg(q2 + j);
    float4 c3 = __ldg(q3 + j);

    #pragma unroll 4
    for (int g = 0; g < NG; g++) {
        float4 n0, n1, n2, n3;
        if (g + 1 < NG) {
            const int idx = (g + 1) * 8 + j;
            n0 = __ldg(q0 + idx);
            n1 = __ldg(q1 + idx);
            n2 = __ldg(q2 + idx);
            n3 = __ldg(q3 + idx);
        }
        if (g + 1 + PF_LEAD < NG) {
            const int pidx = (g + 1 + PF_LEAD) * 8 + j;
            pfL2(q0 + pidx); pfL2(q1 + pidx); pfL2(q2 + pidx); pfL2(q3 + pidx);
        }
        const float* f0 = reinterpret_cast<const float*>(&c0);
        const float* f1 = reinterpret_cast<const float*>(&c1);
        const float* f2 = reinterpret_cast<const float*>(&c2);
        const float* f3 = reinterpret_cast<const float*>(&c3);
        #pragma unroll
        for (int jj = 0; jj < 4; jj++) {
            #pragma unroll
            for (int o = 0; o < 8; o++) {
                float4 w = wsm[o * 512 + g * 32 + jj * 8 + j];  // 128B broadcast LDS
                acc[o] += f0[jj] * w.x + f1[jj] * w.y + f2[jj] * w.z + f3[jj] * w.w;
            }
        }
        if (g + 1 < NG) { c0 = n0; c1 = n1; c2 = n2; c3 = n3; }
    }

    // ---- reduce over the 8 j-lanes (butterfly: all lanes get full sums)
    #pragma unroll
    for (int m = 1; m < 8; m <<= 1) {
        #pragma unroll
        for (int o = 0; o < 8; o++)
            acc[o] += __shfl_xor_sync(0xffffffffu, acc[o], m);
    }

    // ---- per-token epilogue (redundant across the 8 j-lanes)
    float w[4];
    {
        float lt[4], ls[4];
        #pragma unroll
        for (int kp = 0; kp < 4; kp++) {
            lt[kp] = acc[kp]     + __ldg(bt + kp);
            ls[kp] = acc[4 + kp] + __ldg(bs + kp);
        }
        // top-2 (first-index tie semantics like jax top_k)
        int i0 = 0; float v0 = lt[0];
        #pragma unroll
        for (int k = 1; k < 4; k++) if (lt[k] > v0) { v0 = lt[k]; i0 = k; }
        int i1 = -1; float v1 = -3.0e38f;
        #pragma unroll
        for (int k = 0; k < 4; k++) if (k != i0 && lt[k] > v1) { v1 = lt[k]; i1 = k; }
        const float e  = __expf(v1 - v0);
        const float s2 = 1.0f / (1.0f + e);
        const float p0 = s2;
        const float p1 = e * s2;
        const float mx = fmaxf(fmaxf(ls[0], ls[1]), fmaxf(ls[2], ls[3]));
        float es[4];
        #pragma unroll
        for (int k = 0; k < 4; k++) es[k] = __expf(ls[k] - mx);
        const float inv = 1.0f / (es[0] + es[1] + es[2] + es[3]);
        const float a = 1.0f / (1.0f + __expf(-__ldg(alpha)));
        #pragma unroll
        for (int k = 0; k < 4; k++) {
            const float hard = (k == i0) ? p0 : ((k == i1) ? p1 : 0.0f);
            w[k] = a * hard + (1.0f - a) * (es[k] * inv);
        }
    }

    // ---- phase C: weighted sum for this lane's token; L2-hot re-read
    {
        float4* po = reinterpret_cast<float4*>(out + row);
        #pragma unroll 4
        for (int r = 0; r < 16; r++) {
            const int f = j + 8 * r;    // 8 lanes -> 128B contiguous per row
            float4 va = __ldcs(q0 + f);
            float4 vb = __ldcs(q1 + f);
            float4 vc = __ldcs(q2 + f);
            float4 vd = __ldcs(q3 + f);
            float4 o4;
            o4.x = w[0] * va.x + w[1] * vb.x + w[2] * vc.x + w[3] * vd.x;
            o4.y = w[0] * va.y + w[1] * vb.y + w[2] * vc.y + w[3] * vd.y;
            o4.z = w[0] * va.z + w[1] * vb.z + w[2] * vc.z + w[3] * vd.z;
            o4.w = w[0] * va.w + w[1] * vb.w + w[2] * vc.w + w[3] * vd.w;
            po[f] = o4;
        }
    }
}

extern "C" void kernel_launch(void* const* d_in, const int* in_sizes, int n_in,
                              void* d_out, int out_size)
{
    const float* m0    = (const float*)d_in[0];
    const float* m1    = (const float*)d_in[1];
    const float* m2    = (const float*)d_in[2];
    const float* m3    = (const float*)d_in[3];
    const float* W_top = (const float*)d_in[4];
    const float* b_top = (const float*)d_in[5];
    const float* W_sft = (const float*)d_in[6];
    const float* b_sft = (const float*)d_in[7];
    const float* alpha = (const float*)d_in[8];
    float* out = (float*)d_out;

    const int ntok = in_sizes[0] / 512;       // 32768
    const int grid = ntok / TPB_TOK;          // 1024

    cudaFuncSetAttribute(router_kernel,
                         cudaFuncAttributeMaxDynamicSharedMemorySize, SMEM_BYTES);
    router_kernel<<<grid, THREADS, SMEM_BYTES>>>(m0, m1, m2, m3,
                                                 W_top, b_top, W_sft, b_sft,
                                                 alpha, out);
}

// round 13
// speedup vs baseline: 1.0730x; 1.0730x over previous
#include <cuda_runtime.h>
#include <cstdint>
#include <cstddef>

// router_20091857011524: fused 4-way router (GB300 sm_103a) — R11
// Lane-per-token redesign to kill the W-LDS wavefront tax (77% of R9's L1
// budget). lane = token (32 tok/block); warp w owns dims [w*64, w*64+64).
// W reads are fully warp-uniform (1 wavefront). x is transposed through a
// per-warp smem tile: coalesced LDG.128 -> conflict-free scalar STS
// (stride-33: bank = 4j+t distinct) -> stride-1 scalar LDS. Depth-2 LDG
// ring keeps ~6KB/warp in flight. One block/SM (205KB smem) -> 1024 blocks
// = ~7 waves -> per-wave traffic 46MB << L2 -> phase C guaranteed L2-hot.

#define THREADS 256
#define TPB_TOK 32
#define DPW     64            // dims per warp
#define TILE_F  4224          // per-warp tile: [4 mats][32 dims][33] floats
#define WSM_F   16384         // W: 8 o-planes x 512 float4
#define SLOG_F  (WSM_F + 8 * TILE_F)          // 50176
#define SMEM_FLOATS (SLOG_F + 8 * 32 * 9)     // 52480
#define SMEM_BYTES  (SMEM_FLOATS * 4)         // 209920

__global__ __launch_bounds__(THREADS)
void router_kernel(const float* __restrict__ m0, const float* __restrict__ m1,
                   const float* __restrict__ m2, const float* __restrict__ m3,
                   const float* __restrict__ Wt, const float* __restrict__ bt,
                   const float* __restrict__ Ws, const float* __restrict__ bs,
                   const float* __restrict__ alpha, float* __restrict__ out)
{
    extern __shared__ float smem[];
    float4* wsm4 = reinterpret_cast<float4*>(smem);   // [8][512] float4
    float*  slog = smem + SLOG_F;                     // [8][32][9]

    const int tid  = threadIdx.x;
    const int lane = tid & 31;
    const int wrp  = tid >> 5;
    const int t    = lane >> 3;   // 0..3  (LDG/phase-C token-in-round)
    const int j    = lane & 7;    // 0..7  (LDG/phase-C dim slot)

    // ---- stage W once (linear layout; compute reads are uniform anyway)
    {
        const float4* wt4 = reinterpret_cast<const float4*>(Wt);
        const float4* ws4 = reinterpret_cast<const float4*>(Ws);
        #pragma unroll
        for (int rep = 0; rep < 16; rep++) {
            const int i  = tid + rep * THREADS;   // 0..4095
            const int o  = i >> 9;
            const int dd = i & 511;
            wsm4[o * 512 + dd] = (o < 4) ? __ldg(wt4 + o * 512 + dd)
                                         : __ldg(ws4 + (o - 4) * 512 + dd);
        }
    }
    __syncthreads();

    const int tokBase = blockIdx.x * TPB_TOK;
    // LDG bases for this lane's (t, j) slot; round rr adds rr*4 rows = rr*2048 floats
    const size_t rbase = (size_t)(tokBase + t) * 512 + 4 * j;
    const float* b0 = m0 + rbase;
    const float* b1 = m1 + rbase;
    const float* b2 = m2 + rbase;
    const float* b3 = m3 + rbase;

    float* tile = smem + WSM_F + wrp * TILE_F;   // [k][32 dims][33]

    float acc[8];
    #pragma unroll
    for (int o = 0; o < 8; o++) acc[o] = 0.f;

    const int wd0 = wrp * DPW;   // warp's dim base

    #pragma unroll
    for (int g = 0; g < 2; g++) {
        const int d0 = wd0 + g * 32;

        // ---- fill tile: 8 rounds of (4 tokens x 32 dims), depth-2 LDG ring
        float4 ring[3][4];
        #pragma unroll
        for (int rr = 0; rr < 2; rr++) {
            const size_t off = (size_t)rr * 2048 + d0;
            ring[rr][0] = *reinterpret_cast<const float4*>(b0 + off);
            ring[rr][1] = *reinterpret_cast<const float4*>(b1 + off);
            ring[rr][2] = *reinterpret_cast<const float4*>(b2 + off);
            ring[rr][3] = *reinterpret_cast<const float4*>(b3 + off);
        }
        #pragma unroll
        for (int rr = 0; rr < 8; rr++) {
            if (rr + 2 < 8) {
                const size_t off = (size_t)(rr + 2) * 2048 + d0;
                ring[(rr + 2) % 3][0] = *reinterpret_cast<const float4*>(b0 + off);
                ring[(rr + 2) % 3][1] = *reinterpret_cast<const float4*>(b1 + off);
                ring[(rr + 2) % 3][2] = *reinterpret_cast<const float4*>(b2 + off);
                ring[(rr + 2) % 3][3] = *reinterpret_cast<const float4*>(b3 + off);
            }
            // scatter: tile[(k*32 + j*4+e)*33 + tok] — bank 4j+t+e: conflict-free
            const int tokw = rr * 4 + t;
            #pragma unroll
            for (int k = 0; k < 4; k++) {
                const float* v = reinterpret_cast<const float*>(&ring[rr % 3][k]);
                #pragma unroll
                for (int e = 0; e < 4; e++)
                    tile[(k * 32 + j * 4 + e) * 33 + tokw] = v[e];
            }
        }
        __syncwarp();

        // ---- compute: lane = token; W reads fully uniform (1 wavefront)
        #pragma unroll 4
        for (int dd = 0; dd < 32; dd++) {
            const float x0 = tile[(0 * 32 + dd) * 33 + lane];
            const float x1 = tile[(1 * 32 + dd) * 33 + lane];
            const float x2 = tile[(2 * 32 + dd) * 33 + lane];
            const float x3 = tile[(3 * 32 + dd) * 33 + lane];
            #pragma unroll
            for (int o = 0; o < 8; o++) {
                float4 wv = wsm4[o * 512 + d0 + dd];   // uniform broadcast
                acc[o] += x0 * wv.x + x1 * wv.y + x2 * wv.z + x3 * wv.w;
            }
        }
        __syncwarp();   // tile reused by next group
    }

    // ---- cross-warp reduce via slog (lane = token throughout)
    {
        float* sl = slog + (wrp * 32 + lane) * 9;
        #pragma unroll
        for (int o = 0; o < 8; o++) sl[o] = acc[o];
    }
    __syncthreads();

    // ---- per-token epilogue: every lane owns token (tokBase + lane)
    float w[4];
    {
        float lt[4], ls[4];
        #pragma unroll
        for (int kp = 0; kp < 4; kp++) { lt[kp] = __ldg(bt + kp); ls[kp] = __ldg(bs + kp); }
        #pragma unroll
        for (int w2 = 0; w2 < 8; w2++) {
            const float* p = slog + (w2 * 32 + lane) * 9;   // stride 9: conflict-free
            #pragma unroll
            for (int kp = 0; kp < 4; kp++) { lt[kp] += p[kp]; ls[kp] += p[4 + kp]; }
        }
        // top-2 (first-index tie semantics like jax top_k)
        int i0 = 0; float v0 = lt[0];
        #pragma unroll
        for (int k = 1; k < 4; k++) if (lt[k] > v0) { v0 = lt[k]; i0 = k; }
        int i1 = -1; float v1 = -3.0e38f;
        #pragma unroll
        for (int k = 0; k < 4; k++) if (k != i0 && lt[k] > v1) { v1 = lt[k]; i1 = k; }
        const float e  = __expf(v1 - v0);
        const float s2 = 1.0f / (1.0f + e);
        const float p0 = s2;
        const float p1 = e * s2;
        const float mx = fmaxf(fmaxf(ls[0], ls[1]), fmaxf(ls[2], ls[3]));
        float es[4];
        #pragma unroll
        for (int k = 0; k < 4; k++) es[k] = __expf(ls[k] - mx);
        const float inv = 1.0f / (es[0] + es[1] + es[2] + es[3]);
        const float a = 1.0f / (1.0f + __expf(-__ldg(alpha)));
        #pragma unroll
        for (int k = 0; k < 4; k++) {
            const float hard = (k == i0) ? p0 : ((k == i1) ? p1 : 0.0f);
            w[k] = a * hard + (1.0f - a) * (es[k] * inv);
        }
    }

    // ---- phase C: warp handles tokens wrp*4 .. wrp*4+3, j-style coalesced.
    // Fetch that token's weights from the owning lane via shfl.
    {
        const int srcLane = wrp * 4 + t;
        float w0 = __shfl_sync(0xffffffffu, w[0], srcLane);
        float w1 = __shfl_sync(0xffffffffu, w[1], srcLane);
        float w2 = __shfl_sync(0xffffffffu, w[2], srcLane);
        float w3 = __shfl_sync(0xffffffffu, w[3], srcLane);
        const size_t row = (size_t)(tokBase + wrp * 4 + t) * 512;
        const float4* p0_ = reinterpret_cast<const float4*>(m0 + row);
        const float4* p1_ = reinterpret_cast<const float4*>(m1 + row);
        const float4* p2_ = reinterpret_cast<const float4*>(m2 + row);
        const float4* p3_ = reinterpret_cast<const float4*>(m3 + row);
        float4* po = reinterpret_cast<float4*>(out + row);
        #pragma unroll 4
        for (int r = 0; r < 16; r++) {
            const int f = j + 8 * r;   // 8 lanes -> 128B contiguous per row
            float4 va = __ldcs(p0_ + f);
            float4 vb = __ldcs(p1_ + f);
            float4 vc = __ldcs(p2_ + f);
            float4 vd = __ldcs(p3_ + f);
            float4 o4;
            o4.x = w0 * va.x + w1 * vb.x + w2 * vc.x + w3 * vd.x;
            o4.y = w0 * va.y + w1 * vb.y + w2 * vc.y + w3 * vd.y;
            o4.z = w0 * va.z + w1 * vb.z + w2 * vc.z + w3 * vd.z;
            o4.w = w0 * va.w + w1 * vb.w + w2 * vc.w + w3 * vd.w;
            po[f] = o4;
        }
    }
}

extern "C" void kernel_launch(void* const* d_in, const int* in_sizes, int n_in,
                              void* d_out, int out_size)
{
    const float* m0    = (const float*)d_in[0];
    const float* m1    = (const float*)d_in[1];
    const float* m2    = (const float*)d_in[2];
    const float* m3    = (const float*)d_in[3];
    const float* W_top = (const float*)d_in[4];
    const float* b_top = (const float*)d_in[5];
    const float* W_sft = (const float*)d_in[6];
    const float* b_sft = (const float*)d_in[7];
    const float* alpha = (const float*)d_in[8];
    float* out = (float*)d_out;

    const int ntok = in_sizes[0] / 512;       // 32768
    const int grid = ntok / TPB_TOK;          // 1024

    cudaFuncSetAttribute(router_kernel,
                         cudaFuncAttributeMaxDynamicSharedMemorySize, SMEM_BYTES);
    router_kernel<<<grid, THREADS, SMEM_BYTES>>>(m0, m1, m2, m3,
                                                 W_top, b_top, W_sft, b_sft,
                                                 alpha, out);
}